// round 2
// baseline (speedup 1.0000x reference)
#include <cuda_runtime.h>

// Problem constants
#define NG   40      // groups
#define CPG  8       // channels per group (320/40)
#define ND   48      // disparity bins
#define NH   128
#define NW   240
#define NCC  12      // concat channels per tensor
#define PAD  48      // left zero-pad for shifted tgt (>= max d)
#define TROW (NW + PAD)   // 288 floats per padded tgt row
#define HW   (NH * NW)

#define GWC_BLOCKS (NG * NH)                 // 5120
#define CAT_BLOCKS (2 * NCC * ND)            // 1152
#define TOTAL_BLOCKS (GWC_BLOCKS + CAT_BLOCKS)

// ---------------------------------------------------------------------------
// Fused kernel.
//   blocks [0, 5120): groupwise-correlation volume, one block per (g, h).
//     128 threads, 120 active: 30 w-octets x 4 d-quad-groups. Each thread
//     owns an 8w x 4d register tile and k-loops over 3 d-quads (all 48 d).
//     ref stays in registers across all d; tgt window = 3 aligned LDS.128
//     per channel per 32 outputs (12.7 B smem traffic / output).
//   blocks [5120, 6272): concat volume, one block per (c_out, d).
//     d uniform per block -> shift misalignment handled by a uniform
//     register select; all global loads are aligned LDG.128 from L2.
// ---------------------------------------------------------------------------
__global__ __launch_bounds__(128) void fused_kernel(const float* __restrict__ ref,
                                                    const float* __restrict__ tgt,
                                                    const float* __restrict__ refc,
                                                    const float* __restrict__ tgtc,
                                                    float* __restrict__ out) {
    __shared__ __align__(16) float sref[CPG * NW];    // 1920 floats
    __shared__ __align__(16) float stgt[CPG * TROW];  // 2304 floats

    const int tid = threadIdx.x;

    if (blockIdx.x < GWC_BLOCKS) {
        // ================= GWC path =================
        const int g = blockIdx.x / NH;
        const int h = blockIdx.x % NH;

        const float* gref = ref + ((size_t)(g * CPG) * NH + h) * NW;
        const float* gtgt = tgt + ((size_t)(g * CPG) * NH + h) * NW;

        // Cooperative smem loads (all float4, coalesced)
        for (int i = tid; i < CPG * (NW / 4); i += 128) {
            int c = i / (NW / 4), wq = i % (NW / 4);
            float4 v = *(const float4*)(gref + (size_t)c * HW + wq * 4);
            *(float4*)(sref + c * NW + wq * 4) = v;
        }
        for (int i = tid; i < CPG * (PAD / 4); i += 128) {
            int c = i / (PAD / 4), pq = i % (PAD / 4);
            *(float4*)(stgt + c * TROW + pq * 4) = make_float4(0.f, 0.f, 0.f, 0.f);
        }
        for (int i = tid; i < CPG * (NW / 4); i += 128) {
            int c = i / (NW / 4), wq = i % (NW / 4);
            float4 v = *(const float4*)(gtgt + (size_t)c * HW + wq * 4);
            *(float4*)(stgt + c * TROW + PAD + wq * 4) = v;
        }
        __syncthreads();

        if (tid >= 120) return;
        const int dgrp = tid & 3;     // 0..3
        const int oct  = tid >> 2;    // 0..29
        const int w0   = oct * 8;

        // ref[c][w0..w0+7] in registers, reused for all 48 d
        float r[CPG][8];
#pragma unroll
        for (int c = 0; c < CPG; c++) {
            float4 a = *(const float4*)(sref + c * NW + w0);
            float4 b = *(const float4*)(sref + c * NW + w0 + 4);
            r[c][0] = a.x; r[c][1] = a.y; r[c][2] = a.z; r[c][3] = a.w;
            r[c][4] = b.x; r[c][5] = b.y; r[c][6] = b.z; r[c][7] = b.w;
        }

        float* outb = out + (size_t)g * ND * HW + (size_t)h * NW + w0;

#pragma unroll
        for (int k = 0; k < 3; k++) {
            const int d0 = (dgrp + 4 * k) * 4;     // covers all 12 d-quads
            float acc[4][8] = {};
#pragma unroll
            for (int c = 0; c < CPG; c++) {
                // window tgt[w0-d0-4 .. w0-d0+7], aligned (w0-d0 ≡ 0 mod 4)
                const float* tp = stgt + c * TROW + PAD + w0 - d0 - 4;
                float4 v0 = *(const float4*)tp;
                float4 v1 = *(const float4*)(tp + 4);
                float4 v2 = *(const float4*)(tp + 8);
                float wv[12] = {v0.x, v0.y, v0.z, v0.w,
                                v1.x, v1.y, v1.z, v1.w,
                                v2.x, v2.y, v2.z, v2.w};
#pragma unroll
                for (int j = 0; j < 4; j++)
#pragma unroll
                    for (int i = 0; i < 8; i++)
                        acc[j][i] += r[c][i] * wv[i + 4 - j];  // tgt[w0+i-(d0+j)]
            }
#pragma unroll
            for (int j = 0; j < 4; j++) {
                float* op = outb + (size_t)(d0 + j) * HW;
                float4 o0, o1;
                o0.x = acc[j][0] * 0.125f; o0.y = acc[j][1] * 0.125f;
                o0.z = acc[j][2] * 0.125f; o0.w = acc[j][3] * 0.125f;
                o1.x = acc[j][4] * 0.125f; o1.y = acc[j][5] * 0.125f;
                o1.z = acc[j][6] * 0.125f; o1.w = acc[j][7] * 0.125f;
                *(float4*)op       = o0;
                *(float4*)(op + 4) = o1;
            }
        }
    } else {
        // ================= concat path =================
        const int cd = blockIdx.x - GWC_BLOCKS;
        const int c  = cd / ND;       // 0..23
        const int d  = cd % ND;       // uniform per block
        const int s    = d & 3;
        const int dlo  = d - s;

        float* ob = out + ((size_t)(NG + c) * ND + d) * HW;

        if (c < NCC) {
            // ref_concat masked by (w >= d)
            const float* pc = refc + (size_t)c * HW;
            for (int idx = tid; idx < NH * (NW / 4); idx += 128) {
                const int h  = idx / (NW / 4);
                const int w0 = (idx % (NW / 4)) * 4;
                float4 v = *(const float4*)(pc + (size_t)h * NW + w0);
                if (w0 < d) {          // uniform-ish: only low-w columns
                    if (w0 + 0 < d) v.x = 0.f;
                    if (w0 + 1 < d) v.y = 0.f;
                    if (w0 + 2 < d) v.z = 0.f;
                    if (w0 + 3 < d) v.w = 0.f;
                }
                *(float4*)(ob + (size_t)h * NW + w0) = v;
            }
        } else {
            // tgt_concat shifted right by d (zero-fill left)
            const float* pc = tgtc + (size_t)(c - NCC) * HW;
            for (int idx = tid; idx < NH * (NW / 4); idx += 128) {
                const int h  = idx / (NW / 4);
                const int w0 = (idx % (NW / 4)) * 4;
                const float* p = pc + (size_t)h * NW;

                const int a0 = w0 - dlo - 4;                 // aligned window base
                float4 lo = *(const float4*)(p + (a0 < 0 ? 0 : a0));
                float4 hi = *(const float4*)(p + (a0 + 4 < 0 ? 0 : a0 + 4));

                // o[i] = window[i + 4 - s], s uniform per block
                float4 o;
                switch (s) {
                    case 0: o = hi; break;
                    case 1: o = make_float4(lo.w, hi.x, hi.y, hi.z); break;
                    case 2: o = make_float4(lo.z, lo.w, hi.x, hi.y); break;
                    default: o = make_float4(lo.y, lo.z, lo.w, hi.x); break;
                }
                if (w0 < d) {          // zero-fill where w < d
                    if (w0 + 0 < d) o.x = 0.f;
                    if (w0 + 1 < d) o.y = 0.f;
                    if (w0 + 2 < d) o.z = 0.f;
                    if (w0 + 3 < d) o.w = 0.f;
                }
                *(float4*)(ob + (size_t)h * NW + w0) = o;
            }
        }
    }
}

// ---------------------------------------------------------------------------
extern "C" void kernel_launch(void* const* d_in, const int* in_sizes, int n_in,
                              void* d_out, int out_size) {
    (void)in_sizes; (void)n_in; (void)out_size;
    const float* ref_gwc = (const float*)d_in[0];
    const float* tgt_gwc = (const float*)d_in[1];
    const float* ref_c   = (const float*)d_in[2];
    const float* tgt_c   = (const float*)d_in[3];
    float* out = (float*)d_out;

    fused_kernel<<<TOTAL_BLOCKS, 128>>>(ref_gwc, tgt_gwc, ref_c, tgt_c, out);
}

// round 3
// speedup vs baseline: 1.3024x; 1.3024x over previous
#include <cuda_runtime.h>

// Problem constants
#define NG   40      // groups
#define CPG  8       // channels per group (320/40)
#define ND   48      // disparity bins
#define NH   128
#define NW   240
#define NCC  12      // concat channels per tensor
#define PAD  48      // left zero-pad for shifted tgt (>= max d)
#define TROW (NW + PAD)   // 288 floats per padded tgt row
#define HW   (NH * NW)

// ---------------------------------------------------------------------------
// Kernel 1: groupwise-correlation volume. One block per (g, h), 192 threads.
// 180 active threads: 60 w-quads x 3 d-octet groups; k-loop of 2 covers all
// 6 d-octets (48 d). Each thread owns a 4w x 8d register tile:
//   LDS traffic  = 3 aligned LDS.128 / channel / 32 outputs = 12 B/out
//   FMA          = 8 / output
//   state        = r[8][4] + acc[8][4] = 64 regs (vs 96 in the failed R2 tile)
// ---------------------------------------------------------------------------
__global__ __launch_bounds__(192) void gwc_kernel(const float* __restrict__ ref,
                                                  const float* __restrict__ tgt,
                                                  float* __restrict__ out) {
    __shared__ __align__(16) float sref[CPG * NW];    // 1920 floats
    __shared__ __align__(16) float stgt[CPG * TROW];  // 2304 floats

    const int g   = blockIdx.x;
    const int h   = blockIdx.y;
    const int tid = threadIdx.x;

    const float* gref = ref + ((size_t)(g * CPG) * NH + h) * NW;
    const float* gtgt = tgt + ((size_t)(g * CPG) * NH + h) * NW;

    // Cooperative smem loads (float4, coalesced)
    for (int i = tid; i < CPG * (NW / 4); i += 192) {
        int c = i / (NW / 4), wq = i % (NW / 4);
        float4 v = *(const float4*)(gref + (size_t)c * HW + wq * 4);
        *(float4*)(sref + c * NW + wq * 4) = v;
    }
    for (int i = tid; i < CPG * (PAD / 4); i += 192) {
        int c = i / (PAD / 4), pq = i % (PAD / 4);
        *(float4*)(stgt + c * TROW + pq * 4) = make_float4(0.f, 0.f, 0.f, 0.f);
    }
    for (int i = tid; i < CPG * (NW / 4); i += 192) {
        int c = i / (NW / 4), wq = i % (NW / 4);
        float4 v = *(const float4*)(gtgt + (size_t)c * HW + wq * 4);
        *(float4*)(stgt + c * TROW + PAD + wq * 4) = v;
    }
    __syncthreads();

    const int wq   = tid & 63;    // 0..59 active per 64-thread slice
    const int dgrp = tid >> 6;    // 0..2
    if (wq >= NW / 4) return;
    const int w0 = wq * 4;

    // ref[c][w0..w0+3] held in registers across all 48 d
    float r[CPG][4];
#pragma unroll
    for (int c = 0; c < CPG; c++) {
        float4 v = *(const float4*)(sref + c * NW + w0);
        r[c][0] = v.x; r[c][1] = v.y; r[c][2] = v.z; r[c][3] = v.w;
    }

    float* outb = out + (size_t)g * ND * HW + (size_t)h * NW + w0;

#pragma unroll
    for (int k = 0; k < 2; k++) {
        const int d0 = (dgrp + 3 * k) * 8;     // d-octets 0..5 -> all 48 d
        float acc[8][4] = {};
#pragma unroll
        for (int c = 0; c < CPG; c++) {
            // window tgt[w0-d0-8 .. w0-d0+3] (base aligned: w0,d0 mult of 4/8)
            const float* tp = stgt + c * TROW + PAD + w0 - d0 - 8;
            float4 v0 = *(const float4*)tp;
            float4 v1 = *(const float4*)(tp + 4);
            float4 v2 = *(const float4*)(tp + 8);
            float wv[12] = {v0.x, v0.y, v0.z, v0.w,
                            v1.x, v1.y, v1.z, v1.w,
                            v2.x, v2.y, v2.z, v2.w};
#pragma unroll
            for (int j = 0; j < 8; j++)
#pragma unroll
                for (int i = 0; i < 4; i++)
                    acc[j][i] += r[c][i] * wv[i + 8 - j];  // tgt[w0+i-(d0+j)]
        }
#pragma unroll
        for (int j = 0; j < 8; j++) {
            float4 o;
            o.x = acc[j][0] * 0.125f;
            o.y = acc[j][1] * 0.125f;
            o.z = acc[j][2] * 0.125f;
            o.w = acc[j][3] * 0.125f;
            *(float4*)(outb + (size_t)(d0 + j) * HW) = o;
        }
    }
}

// ---------------------------------------------------------------------------
// Kernel 2: concat volume. One block per (c_out, d); d uniform per block so
// the shift misalignment is a uniform register select and every global load
// is an aligned LDG.128 (inputs are L2-resident: 1.47 MB each, 48x reuse).
// ---------------------------------------------------------------------------
__global__ __launch_bounds__(256) void concat_kernel(const float* __restrict__ refc,
                                                     const float* __restrict__ tgtc,
                                                     float* __restrict__ out) {
    const int c = blockIdx.x / ND;   // 0..23
    const int d = blockIdx.x % ND;   // uniform per block
    const int s   = d & 3;
    const int dlo = d - s;
    const int tid = threadIdx.x;

    float* ob = out + ((size_t)(NG + c) * ND + d) * HW;

    if (c < NCC) {
        // ref_concat masked by (w >= d)
        const float* pc = refc + (size_t)c * HW;
        for (int idx = tid; idx < NH * (NW / 4); idx += 256) {
            const int h  = idx / (NW / 4);
            const int w0 = (idx % (NW / 4)) * 4;
            float4 v = *(const float4*)(pc + (size_t)h * NW + w0);
            if (w0 < d) {
                if (w0 + 0 < d) v.x = 0.f;
                if (w0 + 1 < d) v.y = 0.f;
                if (w0 + 2 < d) v.z = 0.f;
                if (w0 + 3 < d) v.w = 0.f;
            }
            *(float4*)(ob + (size_t)h * NW + w0) = v;
        }
    } else {
        // tgt_concat shifted right by d (zero-fill left)
        const float* pc = tgtc + (size_t)(c - NCC) * HW;
        for (int idx = tid; idx < NH * (NW / 4); idx += 256) {
            const int h  = idx / (NW / 4);
            const int w0 = (idx % (NW / 4)) * 4;
            const float* p = pc + (size_t)h * NW;

            const int a0 = w0 - dlo - 4;                 // aligned window base
            float4 lo = *(const float4*)(p + (a0 < 0 ? 0 : a0));
            float4 hi = *(const float4*)(p + (a0 + 4 < 0 ? 0 : a0 + 4));

            float4 o;                                    // o[i] = window[i+4-s]
            switch (s) {
                case 0:  o = hi; break;
                case 1:  o = make_float4(lo.w, hi.x, hi.y, hi.z); break;
                case 2:  o = make_float4(lo.z, lo.w, hi.x, hi.y); break;
                default: o = make_float4(lo.y, lo.z, lo.w, hi.x); break;
            }
            if (w0 < d) {
                if (w0 + 0 < d) o.x = 0.f;
                if (w0 + 1 < d) o.y = 0.f;
                if (w0 + 2 < d) o.z = 0.f;
                if (w0 + 3 < d) o.w = 0.f;
            }
            *(float4*)(ob + (size_t)h * NW + w0) = o;
        }
    }
}

// ---------------------------------------------------------------------------
extern "C" void kernel_launch(void* const* d_in, const int* in_sizes, int n_in,
                              void* d_out, int out_size) {
    (void)in_sizes; (void)n_in; (void)out_size;
    const float* ref_gwc = (const float*)d_in[0];
    const float* tgt_gwc = (const float*)d_in[1];
    const float* ref_c   = (const float*)d_in[2];
    const float* tgt_c   = (const float*)d_in[3];
    float* out = (float*)d_out;

    gwc_kernel<<<dim3(NG, NH), 192>>>(ref_gwc, tgt_gwc, out);
    concat_kernel<<<2 * NCC * ND, 256>>>(ref_c, tgt_c, out);
}